// round 2
// baseline (speedup 1.0000x reference)
#include <cuda_runtime.h>
#include <math.h>

#define N_ROWS 8192
#define F_IN   784
#define H      128

// ---------------- scratch (static device globals; no allocation) -------------
__device__ float  g_o1[N_ROWS * H];     // selu(fc1) activations  (4 MB)
__device__ float2 g_o[N_ROWS];          // final 2-D embedding
__device__ double g_sum[H];
__device__ double g_sumsq[H];
__device__ double g_denom;
__device__ float  g_inv_denom;

// ---------------- helpers ----------------------------------------------------
__device__ __forceinline__ float frcp(float x) {
    float r; asm("rcp.approx.f32 %0, %1;" : "=f"(r) : "f"(x)); return r;
}
__device__ __forceinline__ float selu_f(float v) {
    const float sc = 1.0507009873554805f, al = 1.6732632423543772f;
    return v > 0.f ? sc * v : sc * al * expm1f(v);
}

// ---------------- K1: o1 = selu(x @ fc_w^T + fc_b) ---------------------------
// Tiled fp32 GEMM: BM=64 rows, BN=128 cols (all of H), BK=16. 256 threads,
// per-thread 4x8 accumulator. Pads chosen for conflict-free transposed STS.
#define BM 64
#define BN 128
#define BK 16
__global__ __launch_bounds__(256) void k1_gemm_selu(
    const float* __restrict__ x, const float* __restrict__ w,
    const float* __restrict__ bias)
{
    __shared__ float xs[BK][BM + 2];   // stride 66: 4*66 % 32 == 8 -> no STS conflicts
    __shared__ float ws[BK][BN + 2];   // stride 130: 8*130 % 32 == 16 -> no STS conflicts

    const int t = threadIdx.x;
    if (blockIdx.x == 0 && t < H) { g_sum[t] = 0.0; g_sumsq[t] = 0.0; }

    const int row0 = blockIdx.x * BM;
    const int xr = t >> 2, xc = (t & 3) << 2;   // x tile: 64x16, float4 per thread
    const int wr = t >> 1, wc = (t & 1) << 3;   // w tile: 128x16, 2x float4 per thread
    const int ty = t >> 4, tx = t & 15;         // compute map: rows ty*4.., cols tx*8..

    float acc[4][8];
#pragma unroll
    for (int i = 0; i < 4; i++)
#pragma unroll
        for (int j = 0; j < 8; j++) acc[i][j] = 0.f;

    for (int k0 = 0; k0 < F_IN; k0 += BK) {
        float4 xv = *(const float4*)(x + (size_t)(row0 + xr) * F_IN + k0 + xc);
        xs[xc + 0][xr] = xv.x; xs[xc + 1][xr] = xv.y;
        xs[xc + 2][xr] = xv.z; xs[xc + 3][xr] = xv.w;

        float4 w0 = *(const float4*)(w + (size_t)wr * F_IN + k0 + wc);
        float4 w1 = *(const float4*)(w + (size_t)wr * F_IN + k0 + wc + 4);
        ws[wc + 0][wr] = w0.x; ws[wc + 1][wr] = w0.y;
        ws[wc + 2][wr] = w0.z; ws[wc + 3][wr] = w0.w;
        ws[wc + 4][wr] = w1.x; ws[wc + 5][wr] = w1.y;
        ws[wc + 6][wr] = w1.z; ws[wc + 7][wr] = w1.w;
        __syncthreads();

#pragma unroll
        for (int kk = 0; kk < BK; kk++) {
            float a0 = xs[kk][ty * 4 + 0], a1 = xs[kk][ty * 4 + 1];
            float a2 = xs[kk][ty * 4 + 2], a3 = xs[kk][ty * 4 + 3];
            float b[8];
#pragma unroll
            for (int j = 0; j < 8; j++) b[j] = ws[kk][tx * 8 + j];
#pragma unroll
            for (int j = 0; j < 8; j++) {
                acc[0][j] = fmaf(a0, b[j], acc[0][j]);
                acc[1][j] = fmaf(a1, b[j], acc[1][j]);
                acc[2][j] = fmaf(a2, b[j], acc[2][j]);
                acc[3][j] = fmaf(a3, b[j], acc[3][j]);
            }
        }
        __syncthreads();
    }

#pragma unroll
    for (int i = 0; i < 4; i++) {
        const int row = row0 + ty * 4 + i;
        float4 v0, v1;
        const int col = tx * 8;
        v0.x = selu_f(acc[i][0] + bias[col + 0]);
        v0.y = selu_f(acc[i][1] + bias[col + 1]);
        v0.z = selu_f(acc[i][2] + bias[col + 2]);
        v0.w = selu_f(acc[i][3] + bias[col + 3]);
        v1.x = selu_f(acc[i][4] + bias[col + 4]);
        v1.y = selu_f(acc[i][5] + bias[col + 5]);
        v1.z = selu_f(acc[i][6] + bias[col + 6]);
        v1.w = selu_f(acc[i][7] + bias[col + 7]);
        *(float4*)(g_o1 + (size_t)row * H + col)     = v0;
        *(float4*)(g_o1 + (size_t)row * H + col + 4) = v1;
    }
}

// ---------------- K2: per-column BN statistics -------------------------------
__global__ __launch_bounds__(256) void k2_stats()
{
    const int col = threadIdx.x & (H - 1);
    const int rl  = threadIdx.x >> 7;            // 0 or 1
    const int rend = blockIdx.x * 128 + 128;
    float s = 0.f, s2 = 0.f;
    for (int r = blockIdx.x * 128 + rl; r < rend; r += 2) {
        float v = g_o1[(size_t)r * H + col];
        s += v;
        s2 = fmaf(v, v, s2);
    }
    atomicAdd(&g_sum[col],   (double)s);
    atomicAdd(&g_sumsq[col], (double)s2);
}

// ---------------- K3: BN apply + fc2 + selu -> o[n,2], optional out tail -----
__global__ __launch_bounds__(256) void k3_bn_fc2(
    const float* __restrict__ gamma, const float* __restrict__ beta,
    const float* __restrict__ w2, const float* __restrict__ b2,
    float* __restrict__ out_tail, int write_tail)
{
    __shared__ float s_scale[H], s_shift[H], s_w0[H], s_w1[H];
    const int t = threadIdx.x;
    if (blockIdx.x == 0 && t == 0) g_denom = 0.0;
    if (t < H) {
        double mean = g_sum[t]   / (double)N_ROWS;
        double var  = g_sumsq[t] / (double)N_ROWS - mean * mean;
        float inv = (float)rsqrt(var + 1e-5);
        float sc  = gamma[t] * inv;
        s_scale[t] = sc;
        s_shift[t] = beta[t] - (float)mean * sc;
        s_w0[t] = w2[t];
        s_w1[t] = w2[H + t];
    }
    __syncthreads();

    const int warp = t >> 5, lane = t & 31;
    const int gw = blockIdx.x * 8 + warp;        // 128 blocks * 8 warps = 1024
    const float bb0 = b2[0], bb1 = b2[1];

    for (int row = gw; row < N_ROWS; row += 1024) {
        float4 v = *(const float4*)(g_o1 + (size_t)row * H + lane * 4);
        const int c = lane * 4;
        float d0 = 0.f, d1 = 0.f;
        float bn;
        bn = fmaf(v.x, s_scale[c + 0], s_shift[c + 0]);
        d0 = fmaf(bn, s_w0[c + 0], d0); d1 = fmaf(bn, s_w1[c + 0], d1);
        bn = fmaf(v.y, s_scale[c + 1], s_shift[c + 1]);
        d0 = fmaf(bn, s_w0[c + 1], d0); d1 = fmaf(bn, s_w1[c + 1], d1);
        bn = fmaf(v.z, s_scale[c + 2], s_shift[c + 2]);
        d0 = fmaf(bn, s_w0[c + 2], d0); d1 = fmaf(bn, s_w1[c + 2], d1);
        bn = fmaf(v.w, s_scale[c + 3], s_shift[c + 3]);
        d0 = fmaf(bn, s_w0[c + 3], d0); d1 = fmaf(bn, s_w1[c + 3], d1);
#pragma unroll
        for (int off = 16; off > 0; off >>= 1) {
            d0 += __shfl_down_sync(0xffffffffu, d0, off);
            d1 += __shfl_down_sync(0xffffffffu, d1, off);
        }
        if (lane == 0) {
            float o0 = selu_f(d0 + bb0);
            float o1 = selu_f(d1 + bb1);
            g_o[row] = make_float2(o0, o1);
            if (write_tail) {
                out_tail[row * 2 + 0] = o0;
                out_tail[row * 2 + 1] = o1;
            }
        }
    }
}

// ---------------- K4: denom = sum_{i,j} 1/(1+|pi-pj|^2) ----------------------
__global__ __launch_bounds__(256) void k4_denom()
{
    extern __shared__ float2 sm[];               // 8192 * 8B = 64 KB
    const int t = threadIdx.x;
    for (int i = t; i < N_ROWS; i += 256) sm[i] = g_o[i];
    __syncthreads();

    const int i0 = blockIdx.x * 32;              // grid 256 -> 32 rows each
    float acc = 0.f;
    for (int rr = 0; rr < 8; rr++) {
        float2 p0 = sm[i0 + rr * 4 + 0];
        float2 p1 = sm[i0 + rr * 4 + 1];
        float2 p2 = sm[i0 + rr * 4 + 2];
        float2 p3 = sm[i0 + rr * 4 + 3];
        for (int j = t; j < N_ROWS; j += 256) {
            float2 q = sm[j];
            float dx, dy, d;
            dx = p0.x - q.x; dy = p0.y - q.y; d = fmaf(dx, dx, dy * dy);
            acc += frcp(1.f + d);
            dx = p1.x - q.x; dy = p1.y - q.y; d = fmaf(dx, dx, dy * dy);
            acc += frcp(1.f + d);
            dx = p2.x - q.x; dy = p2.y - q.y; d = fmaf(dx, dx, dy * dy);
            acc += frcp(1.f + d);
            dx = p3.x - q.x; dy = p3.y - q.y; d = fmaf(dx, dx, dy * dy);
            acc += frcp(1.f + d);
        }
    }
    // block reduction
    float s = acc;
#pragma unroll
    for (int off = 16; off > 0; off >>= 1)
        s += __shfl_down_sync(0xffffffffu, s, off);
    __shared__ float red[8];
    if ((t & 31) == 0) red[t >> 5] = s;
    __syncthreads();
    if (t == 0) {
        float tot = 0.f;
#pragma unroll
        for (int u = 0; u < 8; u++) tot += red[u];
        atomicAdd(&g_denom, (double)tot);
    }
}

__global__ void k4b_inv()
{
    g_inv_denom = (float)(1.0 / (g_denom - (double)N_ROWS));
}

// ---------------- K5: qij = (1/(1+dis)) * inv_denom, 268 MB write ------------
__global__ __launch_bounds__(256) void k5_qij(float* __restrict__ out)
{
    extern __shared__ float2 sm[];
    const int t = threadIdx.x;
    for (int i = t; i < N_ROWS; i += 256) sm[i] = g_o[i];
    __syncthreads();

    const float inv = g_inv_denom;
    const int i0 = blockIdx.x * 16;              // grid 512 -> 16 rows each
    for (int r = 0; r < 16; r++) {
        const int i = i0 + r;
        const float2 p = sm[i];
        float4* __restrict__ row = (float4*)(out + (size_t)i * N_ROWS);
        for (int j4 = t; j4 < N_ROWS / 4; j4 += 256) {
            const int j = j4 * 4;
            float2 q0 = sm[j + 0], q1 = sm[j + 1], q2 = sm[j + 2], q3 = sm[j + 3];
            float dx, dy;
            float4 o4;
            dx = p.x - q0.x; dy = p.y - q0.y;
            o4.x = frcp(fmaf(dx, dx, fmaf(dy, dy, 1.f))) * inv;
            dx = p.x - q1.x; dy = p.y - q1.y;
            o4.y = frcp(fmaf(dx, dx, fmaf(dy, dy, 1.f))) * inv;
            dx = p.x - q2.x; dy = p.y - q2.y;
            o4.z = frcp(fmaf(dx, dx, fmaf(dy, dy, 1.f))) * inv;
            dx = p.x - q3.x; dy = p.y - q3.y;
            o4.w = frcp(fmaf(dx, dx, fmaf(dy, dy, 1.f))) * inv;
            row[j4] = o4;
        }
    }
}

// ---------------- launch -----------------------------------------------------
extern "C" void kernel_launch(void* const* d_in, const int* in_sizes, int n_in,
                              void* d_out, int out_size)
{
    const float* x     = (const float*)d_in[0];
    const float* fcw   = (const float*)d_in[1];
    const float* fcb   = (const float*)d_in[2];
    const float* gamma = (const float*)d_in[3];
    const float* beta  = (const float*)d_in[4];
    const float* w2    = (const float*)d_in[5];
    const float* b2    = (const float*)d_in[6];
    float* out = (float*)d_out;

    // opt-in to 64 KB dynamic SMEM for the pairwise kernels (eager, idempotent,
    // legal under graph capture: not a sync, not an allocation)
    cudaFuncSetAttribute(k4_denom, cudaFuncAttributeMaxDynamicSharedMemorySize, 65536);
    cudaFuncSetAttribute(k5_qij,   cudaFuncAttributeMaxDynamicSharedMemorySize, 65536);

    const size_t nq = (size_t)N_ROWS * N_ROWS;
    const int write_tail = ((size_t)out_size > nq) ? 1 : 0;

    k1_gemm_selu<<<N_ROWS / BM, 256>>>(x, fcw, fcb);
    k2_stats<<<N_ROWS / 128, 256>>>();
    k3_bn_fc2<<<128, 256>>>(gamma, beta, w2, b2, out + nq, write_tail);
    k4_denom<<<256, 256, 65536>>>();
    k4b_inv<<<1, 1>>>();
    k5_qij<<<512, 256, 65536>>>(out);
}

// round 4
// speedup vs baseline: 1.0990x; 1.0990x over previous
#include <cuda_runtime.h>
#include <math.h>

#define N_ROWS 8192
#define F_IN   784
#define H      128

// ---------------- scratch (static device globals; no allocation) -------------
__device__ float  g_p0[N_ROWS * H];     // split-K partial 0 (4 MB)
__device__ float  g_p1[N_ROWS * H];     // split-K partial 1 (4 MB)
__device__ float  g_o1[N_ROWS * H];     // selu(fc1) activations (4 MB)
__device__ float2 g_o[N_ROWS];          // final 2-D embedding
__device__ double g_sum[H];
__device__ double g_sumsq[H];
__device__ double g_denom;
__device__ float  g_inv_denom;

// ---------------- helpers ----------------------------------------------------
__device__ __forceinline__ float frcp(float x) {
    float r; asm("rcp.approx.f32 %0, %1;" : "=f"(r) : "f"(x)); return r;
}
__device__ __forceinline__ float selu_f(float v) {
    const float sc = 1.0507009873554805f, al = 1.6732632423543772f;
    return v > 0.f ? sc * v : sc * al * expm1f(v);
}

// ---------------- K1: split-K GEMM partials (no epilogue) --------------------
// grid 256 = 128 row-tiles x 2 K-parts. BM=64, BN=128, BK=16, 256 thr, 4x8 acc.
#define BM 64
#define BN 128
#define BK 16
__global__ __launch_bounds__(256) void k1_gemm(
    const float* __restrict__ x, const float* __restrict__ w)
{
    __shared__ float xs[BK][BM + 2];
    __shared__ float ws[BK][BN + 2];

    const int t = threadIdx.x;
    if (blockIdx.x == 0 && t < H) { g_sum[t] = 0.0; g_sumsq[t] = 0.0; }

    const int row_tile = blockIdx.x & 127;
    const int kp       = blockIdx.x >> 7;
    const int k_begin  = kp ? 384 : 0;
    const int k_iters  = kp ? 25 : 24;          // 384 + 400 = 784
    float* __restrict__ dst = kp ? g_p1 : g_p0;

    const int row0 = row_tile * BM;
    const int xr = t >> 2, xc = (t & 3) << 2;
    const int wr = t >> 1, wc = (t & 1) << 3;
    const int ty = t >> 4, tx = t & 15;

    float acc[4][8];
#pragma unroll
    for (int i = 0; i < 4; i++)
#pragma unroll
        for (int j = 0; j < 8; j++) acc[i][j] = 0.f;

    for (int it = 0; it < k_iters; it++) {
        const int k0 = k_begin + it * BK;
        float4 xv = *(const float4*)(x + (size_t)(row0 + xr) * F_IN + k0 + xc);
        xs[xc + 0][xr] = xv.x; xs[xc + 1][xr] = xv.y;
        xs[xc + 2][xr] = xv.z; xs[xc + 3][xr] = xv.w;

        float4 w0 = *(const float4*)(w + (size_t)wr * F_IN + k0 + wc);
        float4 w1 = *(const float4*)(w + (size_t)wr * F_IN + k0 + wc + 4);
        ws[wc + 0][wr] = w0.x; ws[wc + 1][wr] = w0.y;
        ws[wc + 2][wr] = w0.z; ws[wc + 3][wr] = w0.w;
        ws[wc + 4][wr] = w1.x; ws[wc + 5][wr] = w1.y;
        ws[wc + 6][wr] = w1.z; ws[wc + 7][wr] = w1.w;
        __syncthreads();

#pragma unroll
        for (int kk = 0; kk < BK; kk++) {
            float a0 = xs[kk][ty * 4 + 0], a1 = xs[kk][ty * 4 + 1];
            float a2 = xs[kk][ty * 4 + 2], a3 = xs[kk][ty * 4 + 3];
            float b[8];
#pragma unroll
            for (int j = 0; j < 8; j++) b[j] = ws[kk][tx * 8 + j];
#pragma unroll
            for (int j = 0; j < 8; j++) {
                acc[0][j] = fmaf(a0, b[j], acc[0][j]);
                acc[1][j] = fmaf(a1, b[j], acc[1][j]);
                acc[2][j] = fmaf(a2, b[j], acc[2][j]);
                acc[3][j] = fmaf(a3, b[j], acc[3][j]);
            }
        }
        __syncthreads();
    }

#pragma unroll
    for (int i = 0; i < 4; i++) {
        const int row = row0 + ty * 4 + i;
        const int col = tx * 8;
        float4 v0 = make_float4(acc[i][0], acc[i][1], acc[i][2], acc[i][3]);
        float4 v1 = make_float4(acc[i][4], acc[i][5], acc[i][6], acc[i][7]);
        *(float4*)(dst + (size_t)row * H + col)     = v0;
        *(float4*)(dst + (size_t)row * H + col + 4) = v1;
    }
}

// ---------------- K2: combine partials + bias + selu + BN stats --------------
__global__ __launch_bounds__(256) void k2_combine_stats(
    const float* __restrict__ bias)
{
    const int col = threadIdx.x & (H - 1);
    const int rl  = threadIdx.x >> 7;            // 0 or 1
    const float b = bias[col];
    const int rend = blockIdx.x * 128 + 128;
    float s = 0.f, s2 = 0.f;
    for (int r = blockIdx.x * 128 + rl; r < rend; r += 2) {
        const size_t idx = (size_t)r * H + col;
        float v = selu_f(g_p0[idx] + g_p1[idx] + b);
        g_o1[idx] = v;
        s += v;
        s2 = fmaf(v, v, s2);
    }
    atomicAdd(&g_sum[col],   (double)s);
    atomicAdd(&g_sumsq[col], (double)s2);
}

// ---------------- K3: BN apply + fc2 + selu -> o[n,2], optional out tail -----
__global__ __launch_bounds__(256) void k3_bn_fc2(
    const float* __restrict__ gamma, const float* __restrict__ beta,
    const float* __restrict__ w2, const float* __restrict__ b2,
    float* __restrict__ out_tail, int write_tail)
{
    __shared__ float s_scale[H], s_shift[H], s_w0[H], s_w1[H];
    const int t = threadIdx.x;
    if (blockIdx.x == 0 && t == 0) g_denom = 0.0;
    if (t < H) {
        double mean = g_sum[t]   / (double)N_ROWS;
        double var  = g_sumsq[t] / (double)N_ROWS - mean * mean;
        float inv = (float)rsqrt(var + 1e-5);
        float sc  = gamma[t] * inv;
        s_scale[t] = sc;
        s_shift[t] = beta[t] - (float)mean * sc;
        s_w0[t] = w2[t];
        s_w1[t] = w2[H + t];
    }
    __syncthreads();

    const int warp = t >> 5, lane = t & 31;
    const int gw = blockIdx.x * 8 + warp;        // 128 blocks * 8 warps = 1024
    const float bb0 = b2[0], bb1 = b2[1];

    for (int row = gw; row < N_ROWS; row += 1024) {
        float4 v = *(const float4*)(g_o1 + (size_t)row * H + lane * 4);
        const int c = lane * 4;
        float d0 = 0.f, d1 = 0.f;
        float bn;
        bn = fmaf(v.x, s_scale[c + 0], s_shift[c + 0]);
        d0 = fmaf(bn, s_w0[c + 0], d0); d1 = fmaf(bn, s_w1[c + 0], d1);
        bn = fmaf(v.y, s_scale[c + 1], s_shift[c + 1]);
        d0 = fmaf(bn, s_w0[c + 1], d0); d1 = fmaf(bn, s_w1[c + 1], d1);
        bn = fmaf(v.z, s_scale[c + 2], s_shift[c + 2]);
        d0 = fmaf(bn, s_w0[c + 2], d0); d1 = fmaf(bn, s_w1[c + 2], d1);
        bn = fmaf(v.w, s_scale[c + 3], s_shift[c + 3]);
        d0 = fmaf(bn, s_w0[c + 3], d0); d1 = fmaf(bn, s_w1[c + 3], d1);
#pragma unroll
        for (int off = 16; off > 0; off >>= 1) {
            d0 += __shfl_down_sync(0xffffffffu, d0, off);
            d1 += __shfl_down_sync(0xffffffffu, d1, off);
        }
        if (lane == 0) {
            float o0 = selu_f(d0 + bb0);
            float o1 = selu_f(d1 + bb1);
            g_o[row] = make_float2(o0, o1);
            if (write_tail) {
                out_tail[row * 2 + 0] = o0;
                out_tail[row * 2 + 1] = o1;
            }
        }
    }
}

// ---------------- K4: denom = sum_{i,j} 1/(1+|pi-pj|^2) ----------------------
// 8 rows per q-load, (1+d) folded into FFMA chain, 4 rotating accumulators.
__global__ __launch_bounds__(256) void k4_denom()
{
    extern __shared__ float2 sm[];               // 8192 * 8B = 64 KB
    const int t = threadIdx.x;
    for (int i = t; i < N_ROWS; i += 256) sm[i] = g_o[i];
    __syncthreads();

    const int i0 = blockIdx.x * 32;              // grid 256 -> 32 rows each
    float a[4] = {0.f, 0.f, 0.f, 0.f};
    for (int rr = 0; rr < 4; rr++) {
        float2 p[8];
#pragma unroll
        for (int u = 0; u < 8; u++) p[u] = sm[i0 + rr * 8 + u];
        for (int j = t; j < N_ROWS; j += 256) {
            float2 q = sm[j];
#pragma unroll
            for (int u = 0; u < 8; u++) {
                float dx = p[u].x - q.x;
                float dy = p[u].y - q.y;
                float d  = fmaf(dx, dx, fmaf(dy, dy, 1.f));
                a[u & 3] += frcp(d);
            }
        }
    }
    float s = (a[0] + a[1]) + (a[2] + a[3]);
#pragma unroll
    for (int off = 16; off > 0; off >>= 1)
        s += __shfl_down_sync(0xffffffffu, s, off);
    __shared__ float red[8];
    if ((t & 31) == 0) red[t >> 5] = s;
    __syncthreads();
    if (t == 0) {
        float tot = 0.f;
#pragma unroll
        for (int u = 0; u < 8; u++) tot += red[u];
        atomicAdd(&g_denom, (double)tot);
    }
}

__global__ void k4b_inv()
{
    g_inv_denom = (float)(1.0 / (g_denom - (double)N_ROWS));
}

// ---------------- K5: qij = (1/(1+dis)) * inv_denom, 268 MB write ------------
// 2 rows share each q-load quartet; streaming stores.
__global__ __launch_bounds__(256) void k5_qij(float* __restrict__ out)
{
    extern __shared__ float2 sm[];
    const int t = threadIdx.x;
    for (int i = t; i < N_ROWS; i += 256) sm[i] = g_o[i];
    __syncthreads();

    const float inv = g_inv_denom;
    const int i0 = blockIdx.x * 16;              // grid 512 -> 16 rows each
    for (int r = 0; r < 16; r += 2) {
        const int i = i0 + r;
        const float2 pA = sm[i];
        const float2 pB = sm[i + 1];
        float4* __restrict__ rowA = (float4*)(out + (size_t)i * N_ROWS);
        float4* __restrict__ rowB = (float4*)(out + (size_t)(i + 1) * N_ROWS);
        for (int j4 = t; j4 < N_ROWS / 4; j4 += 256) {
            const int j = j4 * 4;
            float2 q0 = sm[j + 0], q1 = sm[j + 1], q2 = sm[j + 2], q3 = sm[j + 3];
            float dx, dy;
            float4 oA, oB;
            dx = pA.x - q0.x; dy = pA.y - q0.y;
            oA.x = frcp(fmaf(dx, dx, fmaf(dy, dy, 1.f))) * inv;
            dx = pA.x - q1.x; dy = pA.y - q1.y;
            oA.y = frcp(fmaf(dx, dx, fmaf(dy, dy, 1.f))) * inv;
            dx = pA.x - q2.x; dy = pA.y - q2.y;
            oA.z = frcp(fmaf(dx, dx, fmaf(dy, dy, 1.f))) * inv;
            dx = pA.x - q3.x; dy = pA.y - q3.y;
            oA.w = frcp(fmaf(dx, dx, fmaf(dy, dy, 1.f))) * inv;
            dx = pB.x - q0.x; dy = pB.y - q0.y;
            oB.x = frcp(fmaf(dx, dx, fmaf(dy, dy, 1.f))) * inv;
            dx = pB.x - q1.x; dy = pB.y - q1.y;
            oB.y = frcp(fmaf(dx, dx, fmaf(dy, dy, 1.f))) * inv;
            dx = pB.x - q2.x; dy = pB.y - q2.y;
            oB.z = frcp(fmaf(dx, dx, fmaf(dy, dy, 1.f))) * inv;
            dx = pB.x - q3.x; dy = pB.y - q3.y;
            oB.w = frcp(fmaf(dx, dx, fmaf(dy, dy, 1.f))) * inv;
            __stcs(rowA + j4, oA);
            __stcs(rowB + j4, oB);
        }
    }
}

// ---------------- launch -----------------------------------------------------
extern "C" void kernel_launch(void* const* d_in, const int* in_sizes, int n_in,
                              void* d_out, int out_size)
{
    const float* x     = (const float*)d_in[0];
    const float* fcw   = (const float*)d_in[1];
    const float* fcb   = (const float*)d_in[2];
    const float* gamma = (const float*)d_in[3];
    const float* beta  = (const float*)d_in[4];
    const float* w2    = (const float*)d_in[5];
    const float* b2    = (const float*)d_in[6];
    float* out = (float*)d_out;

    cudaFuncSetAttribute(k4_denom, cudaFuncAttributeMaxDynamicSharedMemorySize, 65536);
    cudaFuncSetAttribute(k5_qij,   cudaFuncAttributeMaxDynamicSharedMemorySize, 65536);

    const size_t nq = (size_t)N_ROWS * N_ROWS;
    const int write_tail = ((size_t)out_size > nq) ? 1 : 0;

    k1_gemm<<<256, 256>>>(x, fcw);
    k2_combine_stats<<<N_ROWS / 128, 256>>>(fcb);
    k3_bn_fc2<<<128, 256>>>(gamma, beta, w2, b2, out + nq, write_tail);
    k4_denom<<<256, 256, 65536>>>();
    k4b_inv<<<1, 1>>>();
    k5_qij<<<512, 256, 65536>>>(out);
}

// round 6
// speedup vs baseline: 1.1718x; 1.0662x over previous
#include <cuda_runtime.h>
#include <math.h>

#define N_ROWS 8192
#define F_IN   784
#define H      128
#define JH     4096   // j-half size for pairwise kernels

typedef unsigned long long ull;

// ---------------- scratch (static device globals; no allocation) -------------
__device__ float  g_p0[N_ROWS * H];     // split-K partial 0 (4 MB)
__device__ float  g_p1[N_ROWS * H];     // split-K partial 1 (4 MB)
__device__ float  g_o1[N_ROWS * H];     // selu(fc1) activations (4 MB)
__device__ float2 g_o[N_ROWS];          // final 2-D embedding
__device__ double g_sum[H];
__device__ double g_sumsq[H];
__device__ double g_denom;
__device__ float  g_inv_denom;

// ---------------- helpers ----------------------------------------------------
__device__ __forceinline__ float frcp(float x) {
    float r; asm("rcp.approx.f32 %0, %1;" : "=f"(r) : "f"(x)); return r;
}
__device__ __forceinline__ float selu_f(float v) {
    const float sc = 1.0507009873554805f, al = 1.6732632423543772f;
    return v > 0.f ? sc * v : sc * al * expm1f(v);
}

#define FMA_F32X2(d, a, b, c) \
    asm("fma.rn.f32x2 %0, %1, %2, %3;" : "=l"(d) : "l"(a), "l"(b), "l"(c))
#define PACK_F32X2(out, lo, hi) \
    asm("mov.b64 %0, {%1, %2};" : "=l"(out) : "f"(lo), "f"(hi))
#define UNPACK_F32X2(lo, hi, in) \
    asm("mov.b64 {%0, %1}, %2;" : "=f"(lo), "=f"(hi) : "l"(in))

// ---------------- K1: split-K GEMM partials via packed f32x2 FFMA ------------
// grid 256 = 128 row-tiles x 2 K-parts. BM=64, BN=128, BK=16, 256 thr.
// acc: 4 rows x 4 col-pairs packed u64. Pads +4 keep 16B alignment for LDS.128.
#define BM 64
#define BN 128
#define BK 16
__global__ __launch_bounds__(256) void k1_gemm(
    const float* __restrict__ x, const float* __restrict__ w)
{
    __shared__ float xs[BK][BM + 4];   // stride 68 floats = 272B (16B aligned)
    __shared__ float ws[BK][BN + 4];   // stride 132 floats = 528B (16B aligned)

    const int t = threadIdx.x;
    if (blockIdx.x == 0 && t < H) { g_sum[t] = 0.0; g_sumsq[t] = 0.0; }

    const int row_tile = blockIdx.x & 127;
    const int kp       = blockIdx.x >> 7;
    const int k_begin  = kp ? 384 : 0;
    const int k_iters  = kp ? 25 : 24;          // 384 + 400 = 784
    float* __restrict__ dst = kp ? g_p1 : g_p0;

    const int row0 = row_tile * BM;
    const int xr = t >> 2, xc = (t & 3) << 2;
    const int wr = t >> 1, wc = (t & 1) << 3;
    const int ty = t >> 4, tx = t & 15;

    ull acc2[4][4];
#pragma unroll
    for (int i = 0; i < 4; i++)
#pragma unroll
        for (int j = 0; j < 4; j++) acc2[i][j] = 0ull;

    for (int it = 0; it < k_iters; it++) {
        const int k0 = k_begin + it * BK;
        float4 xv = *(const float4*)(x + (size_t)(row0 + xr) * F_IN + k0 + xc);
        xs[xc + 0][xr] = xv.x; xs[xc + 1][xr] = xv.y;
        xs[xc + 2][xr] = xv.z; xs[xc + 3][xr] = xv.w;

        float4 w0 = *(const float4*)(w + (size_t)wr * F_IN + k0 + wc);
        float4 w1 = *(const float4*)(w + (size_t)wr * F_IN + k0 + wc + 4);
        ws[wc + 0][wr] = w0.x; ws[wc + 1][wr] = w0.y;
        ws[wc + 2][wr] = w0.z; ws[wc + 3][wr] = w0.w;
        ws[wc + 4][wr] = w1.x; ws[wc + 5][wr] = w1.y;
        ws[wc + 6][wr] = w1.z; ws[wc + 7][wr] = w1.w;
        __syncthreads();

#pragma unroll
        for (int kk = 0; kk < BK; kk++) {
            float4 av = *(const float4*)&xs[kk][ty * 4];
            ull a2[4];
            PACK_F32X2(a2[0], av.x, av.x);
            PACK_F32X2(a2[1], av.y, av.y);
            PACK_F32X2(a2[2], av.z, av.z);
            PACK_F32X2(a2[3], av.w, av.w);
            ulonglong2 bA = *(const ulonglong2*)&ws[kk][tx * 8];
            ulonglong2 bB = *(const ulonglong2*)&ws[kk][tx * 8 + 4];
#pragma unroll
            for (int i = 0; i < 4; i++) {
                FMA_F32X2(acc2[i][0], a2[i], bA.x, acc2[i][0]);
                FMA_F32X2(acc2[i][1], a2[i], bA.y, acc2[i][1]);
                FMA_F32X2(acc2[i][2], a2[i], bB.x, acc2[i][2]);
                FMA_F32X2(acc2[i][3], a2[i], bB.y, acc2[i][3]);
            }
        }
        __syncthreads();
    }

#pragma unroll
    for (int i = 0; i < 4; i++) {
        const int row = row0 + ty * 4 + i;
        const int col = tx * 8;
        float4 v0, v1;
        UNPACK_F32X2(v0.x, v0.y, acc2[i][0]);
        UNPACK_F32X2(v0.z, v0.w, acc2[i][1]);
        UNPACK_F32X2(v1.x, v1.y, acc2[i][2]);
        UNPACK_F32X2(v1.z, v1.w, acc2[i][3]);
        *(float4*)(dst + (size_t)row * H + col)     = v0;
        *(float4*)(dst + (size_t)row * H + col + 4) = v1;
    }
}

// ---------------- K2: combine partials + bias + selu + BN stats --------------
__global__ __launch_bounds__(256) void k2_combine_stats(
    const float* __restrict__ bias)
{
    const int col = threadIdx.x & (H - 1);
    const int rl  = threadIdx.x >> 7;            // 0 or 1
    const float b = bias[col];
    const int rend = blockIdx.x * 128 + 128;
    float s = 0.f, s2 = 0.f;
    for (int r = blockIdx.x * 128 + rl; r < rend; r += 2) {
        const size_t idx = (size_t)r * H + col;
        float v = selu_f(g_p0[idx] + g_p1[idx] + b);
        g_o1[idx] = v;
        s += v;
        s2 = fmaf(v, v, s2);
    }
    atomicAdd(&g_sum[col],   (double)s);
    atomicAdd(&g_sumsq[col], (double)s2);
}

// ---------------- K3: BN apply + fc2 + selu -> o[n,2], optional out tail -----
__global__ __launch_bounds__(256) void k3_bn_fc2(
    const float* __restrict__ gamma, const float* __restrict__ beta,
    const float* __restrict__ w2, const float* __restrict__ b2,
    float* __restrict__ out_tail, int write_tail)
{
    __shared__ float s_scale[H], s_shift[H], s_w0[H], s_w1[H];
    const int t = threadIdx.x;
    if (blockIdx.x == 0 && t == 0) g_denom = 0.0;
    if (t < H) {
        double mean = g_sum[t]   / (double)N_ROWS;
        double var  = g_sumsq[t] / (double)N_ROWS - mean * mean;
        float inv = (float)rsqrt(var + 1e-5);
        float sc  = gamma[t] * inv;
        s_scale[t] = sc;
        s_shift[t] = beta[t] - (float)mean * sc;
        s_w0[t] = w2[t];
        s_w1[t] = w2[H + t];
    }
    __syncthreads();

    const int warp = t >> 5, lane = t & 31;
    const int gw = blockIdx.x * 8 + warp;        // 128 blocks * 8 warps = 1024
    const float bb0 = b2[0], bb1 = b2[1];

    for (int row = gw; row < N_ROWS; row += 1024) {
        float4 v = *(const float4*)(g_o1 + (size_t)row * H + lane * 4);
        const int c = lane * 4;
        float d0 = 0.f, d1 = 0.f;
        float bn;
        bn = fmaf(v.x, s_scale[c + 0], s_shift[c + 0]);
        d0 = fmaf(bn, s_w0[c + 0], d0); d1 = fmaf(bn, s_w1[c + 0], d1);
        bn = fmaf(v.y, s_scale[c + 1], s_shift[c + 1]);
        d0 = fmaf(bn, s_w0[c + 1], d0); d1 = fmaf(bn, s_w1[c + 1], d1);
        bn = fmaf(v.z, s_scale[c + 2], s_shift[c + 2]);
        d0 = fmaf(bn, s_w0[c + 2], d0); d1 = fmaf(bn, s_w1[c + 2], d1);
        bn = fmaf(v.w, s_scale[c + 3], s_shift[c + 3]);
        d0 = fmaf(bn, s_w0[c + 3], d0); d1 = fmaf(bn, s_w1[c + 3], d1);
#pragma unroll
        for (int off = 16; off > 0; off >>= 1) {
            d0 += __shfl_down_sync(0xffffffffu, d0, off);
            d1 += __shfl_down_sync(0xffffffffu, d1, off);
        }
        if (lane == 0) {
            float o0 = selu_f(d0 + bb0);
            float o1 = selu_f(d1 + bb1);
            g_o[row] = make_float2(o0, o1);
            if (write_tail) {
                out_tail[row * 2 + 0] = o0;
                out_tail[row * 2 + 1] = o1;
            }
        }
    }
}

// ---------------- K4: denom via f32x2 distances + paired reciprocal ----------
// grid 2048 = 1024 row-strips(8 rows) x 2 j-halves. 32 KB smem -> 7 blocks/SM.
__global__ __launch_bounds__(256) void k4_denom()
{
    __shared__ float sx[JH], sy[JH];
    const int t    = threadIdx.x;
    const int half = blockIdx.x & 1;
    const int rid  = blockIdx.x >> 1;

    const float2* __restrict__ src = g_o + half * JH;
    for (int i = t; i < JH; i += 256) {
        float2 v = src[i];
        sx[i] = v.x; sy[i] = v.y;
    }

    ull ppx[8], ppy[8], m1, on;
    PACK_F32X2(m1, -1.f, -1.f);
    PACK_F32X2(on,  1.f,  1.f);
#pragma unroll
    for (int u = 0; u < 8; u++) {
        float2 p = g_o[rid * 8 + u];
        PACK_F32X2(ppx[u], p.x, p.x);
        PACK_F32X2(ppy[u], p.y, p.y);
    }
    __syncthreads();

    float a[4] = {0.f, 0.f, 0.f, 0.f};
    for (int jp = t; jp < JH / 2; jp += 256) {
        ull qx = *(const ull*)&sx[jp * 2];
        ull qy = *(const ull*)&sy[jp * 2];
#pragma unroll
        for (int u = 0; u < 8; u++) {
            ull dx2, dy2, t2, d2;
            FMA_F32X2(dx2, qx, m1, ppx[u]);      // p.x - q.x (pair)
            FMA_F32X2(dy2, qy, m1, ppy[u]);
            FMA_F32X2(t2, dy2, dy2, on);         // dy^2 + 1
            FMA_F32X2(d2, dx2, dx2, t2);         // {dA, dB}
            float va, vb;
            UNPACK_F32X2(va, vb, d2);
            float pr = va * vb;
            float sm = va + vb;
            a[u & 3] = fmaf(sm, frcp(pr), a[u & 3]);  // 1/dA + 1/dB
        }
    }

    float s = (a[0] + a[1]) + (a[2] + a[3]);
#pragma unroll
    for (int off = 16; off > 0; off >>= 1)
        s += __shfl_down_sync(0xffffffffu, s, off);
    __shared__ float red[8];
    if ((t & 31) == 0) red[t >> 5] = s;
    __syncthreads();
    if (t == 0) {
        float tot = 0.f;
#pragma unroll
        for (int u = 0; u < 8; u++) tot += red[u];
        atomicAdd(&g_denom, (double)tot);
    }
}

__global__ void k4b_inv()
{
    g_inv_denom = (float)(1.0 / (g_denom - (double)N_ROWS));
}

// ---------------- K5: qij write, same strip/half decomposition ---------------
__global__ __launch_bounds__(256) void k5_qij(float* __restrict__ out)
{
    __shared__ float sx[JH], sy[JH];
    const int t    = threadIdx.x;
    const int half = blockIdx.x & 1;
    const int rid  = blockIdx.x >> 1;

    const float2* __restrict__ src = g_o + half * JH;
    for (int i = t; i < JH; i += 256) {
        float2 v = src[i];
        sx[i] = v.x; sy[i] = v.y;
    }
    __syncthreads();

    const float inv = g_inv_denom;
    ull m1, on;
    PACK_F32X2(m1, -1.f, -1.f);
    PACK_F32X2(on,  1.f,  1.f);

#pragma unroll
    for (int r = 0; r < 8; r++) {
        const int row = rid * 8 + r;
        float2 p = g_o[row];
        ull ppx, ppy;
        PACK_F32X2(ppx, p.x, p.x);
        PACK_F32X2(ppy, p.y, p.y);
        float4* __restrict__ dst = (float4*)(out + (size_t)row * N_ROWS + half * JH);
        for (int c = t; c < JH / 4; c += 256) {
            ull qx0 = *(const ull*)&sx[c * 4];
            ull qx1 = *(const ull*)&sx[c * 4 + 2];
            ull qy0 = *(const ull*)&sy[c * 4];
            ull qy1 = *(const ull*)&sy[c * 4 + 2];
            ull dxA, dyA, tA, dA, dxB, dyB, tB, dB;
            FMA_F32X2(dxA, qx0, m1, ppx);
            FMA_F32X2(dyA, qy0, m1, ppy);
            FMA_F32X2(tA, dyA, dyA, on);
            FMA_F32X2(dA, dxA, dxA, tA);
            FMA_F32X2(dxB, qx1, m1, ppx);
            FMA_F32X2(dyB, qy1, m1, ppy);
            FMA_F32X2(tB, dyB, dyB, on);
            FMA_F32X2(dB, dxB, dxB, tB);
            float d0, d1, d2, d3;
            UNPACK_F32X2(d0, d1, dA);
            UNPACK_F32X2(d2, d3, dB);
            float4 o4;
            o4.x = frcp(d0) * inv;
            o4.y = frcp(d1) * inv;
            o4.z = frcp(d2) * inv;
            o4.w = frcp(d3) * inv;
            __stcs(dst + c, o4);
        }
    }
}

// ---------------- launch -----------------------------------------------------
extern "C" void kernel_launch(void* const* d_in, const int* in_sizes, int n_in,
                              void* d_out, int out_size)
{
    const float* x     = (const float*)d_in[0];
    const float* fcw   = (const float*)d_in[1];
    const float* fcb   = (const float*)d_in[2];
    const float* gamma = (const float*)d_in[3];
    const float* beta  = (const float*)d_in[4];
    const float* w2    = (const float*)d_in[5];
    const float* b2    = (const float*)d_in[6];
    float* out = (float*)d_out;

    const size_t nq = (size_t)N_ROWS * N_ROWS;
    const int write_tail = ((size_t)out_size > nq) ? 1 : 0;

    k1_gemm<<<256, 256>>>(x, fcw);
    k2_combine_stats<<<N_ROWS / 128, 256>>>(fcb);
    k3_bn_fc2<<<128, 256>>>(gamma, beta, w2, b2, out + nq, write_tail);
    k4_denom<<<2048, 256>>>();
    k4b_inv<<<1, 1>>>();
    k5_qij<<<2048, 256>>>(out);
}

// round 9
// speedup vs baseline: 1.5068x; 1.2860x over previous
#include <cuda_runtime.h>
#include <cuda_bf16.h>
#include <mma.h>
#include <stdint.h>
#include <math.h>

using namespace nvcuda;

#define N_ROWS 8192
#define F_IN   784
#define KPAD   800    // F_IN padded to multiple of 32
#define H      128
#define JH     4096   // j-half size for pairwise kernels

typedef unsigned long long ull;

// ---------------- scratch (static device globals; no allocation) -------------
__device__ float         g_o1[N_ROWS * H];   // fc1 raw then activated (4 MB)
__device__ __nv_bfloat16 g_wh[H * KPAD];     // w hi split, zero-padded (200 KB)
__device__ __nv_bfloat16 g_wl[H * KPAD];     // w lo split (200 KB)
__device__ float2 g_o[N_ROWS];               // final 2-D embedding
__device__ double g_sum[H];
__device__ double g_sumsq[H];
__device__ double g_denom;

// ---------------- helpers ----------------------------------------------------
__device__ __forceinline__ float frcp(float x) {
    float r; asm("rcp.approx.f32 %0, %1;" : "=f"(r) : "f"(x)); return r;
}
__device__ __forceinline__ float selu_f(float v) {
    const float sc = 1.0507009873554805f, al = 1.6732632423543772f;
    return v > 0.f ? sc * v : sc * al * expm1f(v);
}

#define FMA_F32X2(d, a, b, c) \
    asm("fma.rn.f32x2 %0, %1, %2, %3;" : "=l"(d) : "l"(a), "l"(b), "l"(c))
#define PACK_F32X2(out, lo, hi) \
    asm("mov.b64 %0, {%1, %2};" : "=l"(out) : "f"(lo), "f"(hi))
#define UNPACK_F32X2(lo, hi, in) \
    asm("mov.b64 {%0, %1}, %2;" : "=f"(lo), "=f"(hi) : "l"(in))

// ---------------- K0: split w into bf16 hi/lo, zero-padded to KPAD -----------
__global__ __launch_bounds__(256) void k0_wprep(const float* __restrict__ w)
{
    // pairs: H * KPAD/2 = 128 * 400 = 51200; grid 64 x 256 -> 800/block... 3.125 iters
    const int total = H * (KPAD / 2);
    for (int e = blockIdx.x * 256 + threadIdx.x; e < total; e += 64 * 256) {
        const int n  = e / (KPAD / 2);
        const int kp = (e % (KPAD / 2)) * 2;
        float2 v = make_float2(0.f, 0.f);
        if (kp < F_IN) v = *(const float2*)(w + (size_t)n * F_IN + kp);
        __nv_bfloat162 hi2 = __floats2bfloat162_rn(v.x, v.y);
        float2 hf = __bfloat1622float2(hi2);
        __nv_bfloat162 lo2 = __floats2bfloat162_rn(v.x - hf.x, v.y - hf.y);
        *(__nv_bfloat162*)(g_wh + (size_t)n * KPAD + kp) = hi2;
        *(__nv_bfloat162*)(g_wl + (size_t)n * KPAD + kp) = lo2;
    }
}

// ---------------- K1: o1_raw = x @ w^T via wmma bf16 2-term split ------------
// 128 blocks (M=64 each), 256 thr = 8 warps, warp tile 16x64. BK=32, 25 chunks.
#define BK 32
#define NCH (KPAD / BK)   // 25
#define LDS_T 40          // 32 + 8 pad (bf16 elems)

__global__ __launch_bounds__(256) void k1_gemm_wmma(const float* __restrict__ x)
{
    __shared__ __nv_bfloat16 sAh[64][LDS_T];
    __shared__ __nv_bfloat16 sAl[64][LDS_T];
    __shared__ __nv_bfloat16 sBh[128][LDS_T];
    __shared__ __nv_bfloat16 sBl[128][LDS_T];

    const int t = threadIdx.x;
    const int wid = t >> 5;
    const int wr = wid >> 1;           // 0..3  (M quadrant, 16 rows)
    const int wc = wid & 1;            // 0..1  (N half, 64 cols)
    const int row0 = blockIdx.x * 64;

    if (blockIdx.x == 0 && t < H) { g_sum[t] = 0.0; g_sumsq[t] = 0.0; }

    wmma::fragment<wmma::accumulator, 16, 16, 16, float> acc[4];
#pragma unroll
    for (int j = 0; j < 4; j++) wmma::fill_fragment(acc[j], 0.f);

    for (int c = 0; c < NCH; c++) {
        const int kc = c * BK;
        // A: convert 64x32 fp32 -> bf16 hi/lo pairs (1024 bf162 pairs, 4/thread)
#pragma unroll
        for (int it = 0; it < 4; it++) {
            const int e = t + it * 256;
            const int m  = e >> 4;
            const int kp = (e & 15) * 2;
            const int k  = kc + kp;
            float2 v = make_float2(0.f, 0.f);
            if (k < F_IN) v = *(const float2*)(x + (size_t)(row0 + m) * F_IN + k);
            __nv_bfloat162 hi2 = __floats2bfloat162_rn(v.x, v.y);
            float2 hf = __bfloat1622float2(hi2);
            __nv_bfloat162 lo2 = __floats2bfloat162_rn(v.x - hf.x, v.y - hf.y);
            *(__nv_bfloat162*)(&sAh[m][kp]) = hi2;
            *(__nv_bfloat162*)(&sAl[m][kp]) = lo2;
        }
        // B: copy 128x32 prepped bf16 hi/lo (2048 pairs, 8/thread)
#pragma unroll
        for (int it = 0; it < 8; it++) {
            const int e = t + it * 256;
            const int n  = e >> 4;
            const int kp = (e & 15) * 2;
            const size_t gi = (size_t)n * KPAD + kc + kp;
            *(uint32_t*)(&sBh[n][kp]) = *(const uint32_t*)(g_wh + gi);
            *(uint32_t*)(&sBl[n][kp]) = *(const uint32_t*)(g_wl + gi);
        }
        __syncthreads();

#pragma unroll
        for (int kk = 0; kk < 2; kk++) {
            wmma::fragment<wmma::matrix_a, 16, 16, 16, __nv_bfloat16, wmma::row_major> ah, al;
            wmma::load_matrix_sync(ah, &sAh[wr * 16][kk * 16], LDS_T);
            wmma::load_matrix_sync(al, &sAl[wr * 16][kk * 16], LDS_T);
#pragma unroll
            for (int j = 0; j < 4; j++) {
                wmma::fragment<wmma::matrix_b, 16, 16, 16, __nv_bfloat16, wmma::col_major> bh, bl;
                wmma::load_matrix_sync(bh, &sBh[wc * 64 + j * 16][kk * 16], LDS_T);
                wmma::load_matrix_sync(bl, &sBl[wc * 64 + j * 16][kk * 16], LDS_T);
                wmma::mma_sync(acc[j], ah, bh, acc[j]);
                wmma::mma_sync(acc[j], ah, bl, acc[j]);
                wmma::mma_sync(acc[j], al, bh, acc[j]);
            }
        }
        __syncthreads();
    }

#pragma unroll
    for (int j = 0; j < 4; j++) {
        float* dst = g_o1 + (size_t)(row0 + wr * 16) * H + wc * 64 + j * 16;
        wmma::store_matrix_sync(dst, acc[j], H, wmma::mem_row_major);
    }
}

// ---------------- K2: bias + selu + BN stats (in-place on g_o1) --------------
__global__ __launch_bounds__(256) void k2_stats(const float* __restrict__ bias)
{
    const int col = threadIdx.x & (H - 1);
    const int rl  = threadIdx.x >> 7;            // 0 or 1
    const float b = bias[col];
    const int rend = blockIdx.x * 128 + 128;
    float s = 0.f, s2 = 0.f;
    for (int r = blockIdx.x * 128 + rl; r < rend; r += 2) {
        const size_t idx = (size_t)r * H + col;
        float v = selu_f(g_o1[idx] + b);
        g_o1[idx] = v;
        s += v;
        s2 = fmaf(v, v, s2);
    }
    atomicAdd(&g_sum[col],   (double)s);
    atomicAdd(&g_sumsq[col], (double)s2);
}

// ---------------- K3: BN apply + fc2 + selu -> o[n,2], optional out tail -----
__global__ __launch_bounds__(256) void k3_bn_fc2(
    const float* __restrict__ gamma, const float* __restrict__ beta,
    const float* __restrict__ w2, const float* __restrict__ b2,
    float* __restrict__ out_tail, int write_tail)
{
    __shared__ float s_scale[H], s_shift[H], s_w0[H], s_w1[H];
    const int t = threadIdx.x;
    if (blockIdx.x == 0 && t == 0) g_denom = 0.0;
    if (t < H) {
        double mean = g_sum[t]   / (double)N_ROWS;
        double var  = g_sumsq[t] / (double)N_ROWS - mean * mean;
        float inv = (float)rsqrt(var + 1e-5);
        float sc  = gamma[t] * inv;
        s_scale[t] = sc;
        s_shift[t] = beta[t] - (float)mean * sc;
        s_w0[t] = w2[t];
        s_w1[t] = w2[H + t];
    }
    __syncthreads();

    const int warp = t >> 5, lane = t & 31;
    const int gw = blockIdx.x * 8 + warp;        // 128 blocks * 8 warps = 1024
    const float bb0 = b2[0], bb1 = b2[1];

    for (int row = gw; row < N_ROWS; row += 1024) {
        float4 v = *(const float4*)(g_o1 + (size_t)row * H + lane * 4);
        const int c = lane * 4;
        float d0 = 0.f, d1 = 0.f;
        float bn;
        bn = fmaf(v.x, s_scale[c + 0], s_shift[c + 0]);
        d0 = fmaf(bn, s_w0[c + 0], d0); d1 = fmaf(bn, s_w1[c + 0], d1);
        bn = fmaf(v.y, s_scale[c + 1], s_shift[c + 1]);
        d0 = fmaf(bn, s_w0[c + 1], d0); d1 = fmaf(bn, s_w1[c + 1], d1);
        bn = fmaf(v.z, s_scale[c + 2], s_shift[c + 2]);
        d0 = fmaf(bn, s_w0[c + 2], d0); d1 = fmaf(bn, s_w1[c + 2], d1);
        bn = fmaf(v.w, s_scale[c + 3], s_shift[c + 3]);
        d0 = fmaf(bn, s_w0[c + 3], d0); d1 = fmaf(bn, s_w1[c + 3], d1);
#pragma unroll
        for (int off = 16; off > 0; off >>= 1) {
            d0 += __shfl_down_sync(0xffffffffu, d0, off);
            d1 += __shfl_down_sync(0xffffffffu, d1, off);
        }
        if (lane == 0) {
            float o0 = selu_f(d0 + bb0);
            float o1 = selu_f(d1 + bb1);
            g_o[row] = make_float2(o0, o1);
            if (write_tail) {
                out_tail[row * 2 + 0] = o0;
                out_tail[row * 2 + 1] = o1;
            }
        }
    }
}

// ---------------- K4: denom via f32x2 distances + paired reciprocal ----------
__global__ __launch_bounds__(256) void k4_denom()
{
    __shared__ float sx[JH], sy[JH];
    const int t    = threadIdx.x;
    const int half = blockIdx.x & 1;
    const int rid  = blockIdx.x >> 1;

    const float2* __restrict__ src = g_o + half * JH;
    for (int i = t; i < JH; i += 256) {
        float2 v = src[i];
        sx[i] = v.x; sy[i] = v.y;
    }

    ull ppx[8], ppy[8], m1, on;
    PACK_F32X2(m1, -1.f, -1.f);
    PACK_F32X2(on,  1.f,  1.f);
#pragma unroll
    for (int u = 0; u < 8; u++) {
        float2 p = g_o[rid * 8 + u];
        PACK_F32X2(ppx[u], p.x, p.x);
        PACK_F32X2(ppy[u], p.y, p.y);
    }
    __syncthreads();

    float a[4] = {0.f, 0.f, 0.f, 0.f};
    for (int jp = t; jp < JH / 2; jp += 256) {
        ull qx = *(const ull*)&sx[jp * 2];
        ull qy = *(const ull*)&sy[jp * 2];
#pragma unroll
        for (int u = 0; u < 8; u++) {
            ull dx2, dy2, t2, d2;
            FMA_F32X2(dx2, qx, m1, ppx[u]);
            FMA_F32X2(dy2, qy, m1, ppy[u]);
            FMA_F32X2(t2, dy2, dy2, on);
            FMA_F32X2(d2, dx2, dx2, t2);
            float va, vb;
            UNPACK_F32X2(va, vb, d2);
            float pr = va * vb;
            float sm = va + vb;
            a[u & 3] = fmaf(sm, frcp(pr), a[u & 3]);
        }
    }

    float s = (a[0] + a[1]) + (a[2] + a[3]);
#pragma unroll
    for (int off = 16; off > 0; off >>= 1)
        s += __shfl_down_sync(0xffffffffu, s, off);
    __shared__ float red[8];
    if ((t & 31) == 0) red[t >> 5] = s;
    __syncthreads();
    if (t == 0) {
        float tot = 0.f;
#pragma unroll
        for (int u = 0; u < 8; u++) tot += red[u];
        atomicAdd(&g_denom, (double)tot);
    }
}

// ---------------- K5: qij write (inv folded in) ------------------------------
__global__ __launch_bounds__(256) void k5_qij(float* __restrict__ out)
{
    __shared__ float sx[JH], sy[JH];
    __shared__ float s_inv;
    const int t    = threadIdx.x;
    const int half = blockIdx.x & 1;
    const int rid  = blockIdx.x >> 1;

    if (t == 0) s_inv = (float)(1.0 / (g_denom - (double)N_ROWS));
    const float2* __restrict__ src = g_o + half * JH;
    for (int i = t; i < JH; i += 256) {
        float2 v = src[i];
        sx[i] = v.x; sy[i] = v.y;
    }
    __syncthreads();

    const float inv = s_inv;
    ull m1, on;
    PACK_F32X2(m1, -1.f, -1.f);
    PACK_F32X2(on,  1.f,  1.f);

#pragma unroll
    for (int r = 0; r < 8; r++) {
        const int row = rid * 8 + r;
        float2 p = g_o[row];
        ull ppx, ppy;
        PACK_F32X2(ppx, p.x, p.x);
        PACK_F32X2(ppy, p.y, p.y);
        float4* __restrict__ dst = (float4*)(out + (size_t)row * N_ROWS + half * JH);
        for (int c = t; c < JH / 4; c += 256) {
            ull qx0 = *(const ull*)&sx[c * 4];
            ull qx1 = *(const ull*)&sx[c * 4 + 2];
            ull qy0 = *(const ull*)&sy[c * 4];
            ull qy1 = *(const ull*)&sy[c * 4 + 2];
            ull dxA, dyA, tA, dA, dxB, dyB, tB, dB;
            FMA_F32X2(dxA, qx0, m1, ppx);
            FMA_F32X2(dyA, qy0, m1, ppy);
            FMA_F32X2(tA, dyA, dyA, on);
            FMA_F32X2(dA, dxA, dxA, tA);
            FMA_F32X2(dxB, qx1, m1, ppx);
            FMA_F32X2(dyB, qy1, m1, ppy);
            FMA_F32X2(tB, dyB, dyB, on);
            FMA_F32X2(dB, dxB, dxB, tB);
            float d0, d1, d2, d3;
            UNPACK_F32X2(d0, d1, dA);
            UNPACK_F32X2(d2, d3, dB);
            float4 o4;
            o4.x = frcp(d0) * inv;
            o4.y = frcp(d1) * inv;
            o4.z = frcp(d2) * inv;
            o4.w = frcp(d3) * inv;
            __stcs(dst + c, o4);
        }
    }
}

// ---------------- launch -----------------------------------------------------
extern "C" void kernel_launch(void* const* d_in, const int* in_sizes, int n_in,
                              void* d_out, int out_size)
{
    const float* x     = (const float*)d_in[0];
    const float* fcw   = (const float*)d_in[1];
    const float* fcb   = (const float*)d_in[2];
    const float* gamma = (const float*)d_in[3];
    const float* beta  = (const float*)d_in[4];
    const float* w2    = (const float*)d_in[5];
    const float* b2    = (const float*)d_in[6];
    float* out = (float*)d_out;

    const size_t nq = (size_t)N_ROWS * N_ROWS;
    const int write_tail = ((size_t)out_size > nq) ? 1 : 0;

    k0_wprep<<<64, 256>>>(fcw);
    k1_gemm_wmma<<<128, 256>>>(x);
    k2_stats<<<N_ROWS / 128, 256>>>(fcb);
    k3_bn_fc2<<<128, 256>>>(gamma, beta, w2, b2, out + nq, write_tail);
    k4_denom<<<2048, 256>>>();
    k5_qij<<<2048, 256>>>(out);
}

// round 10
// speedup vs baseline: 1.7746x; 1.1777x over previous
#include <cuda_runtime.h>
#include <cuda_bf16.h>
#include <mma.h>
#include <stdint.h>
#include <math.h>

using namespace nvcuda;

#define N_ROWS 8192
#define F_IN   784
#define KPAD   800    // F_IN padded to multiple of 32
#define H      128
#define JH     4096   // j-half size for k5
#define JT     1024   // j-tile size for k4

typedef unsigned long long ull;

// ---------------- scratch (static device globals; no allocation) -------------
__device__ float         g_o1[N_ROWS * H];   // fc1 raw then activated (4 MB)
__device__ __nv_bfloat16 g_wh[H * KPAD];     // w hi split, zero-padded
__device__ __nv_bfloat16 g_wl[H * KPAD];     // w lo split
__device__ float2 g_o[N_ROWS];               // final 2-D embedding
__device__ double g_sum[H];
__device__ double g_sumsq[H];
__device__ double g_denom;                   // S = sum_{i<j} 1/(1+d_ij)

// ---------------- helpers ----------------------------------------------------
__device__ __forceinline__ float frcp(float x) {
    float r; asm("rcp.approx.f32 %0, %1;" : "=f"(r) : "f"(x)); return r;
}
__device__ __forceinline__ float selu_f(float v) {
    const float sc = 1.0507009873554805f, al = 1.6732632423543772f;
    return v > 0.f ? sc * v : sc * al * expm1f(v);
}

#define FMA_F32X2(d, a, b, c) \
    asm("fma.rn.f32x2 %0, %1, %2, %3;" : "=l"(d) : "l"(a), "l"(b), "l"(c))
#define PACK_F32X2(out, lo, hi) \
    asm("mov.b64 %0, {%1, %2};" : "=l"(out) : "f"(lo), "f"(hi))
#define UNPACK_F32X2(lo, hi, in) \
    asm("mov.b64 {%0, %1}, %2;" : "=f"(lo), "=f"(hi) : "l"(in))

// ---------------- K0: split w into bf16 hi/lo, zero-padded to KPAD -----------
__global__ __launch_bounds__(256) void k0_wprep(const float* __restrict__ w)
{
    const int total = H * (KPAD / 2);
    for (int e = blockIdx.x * 256 + threadIdx.x; e < total; e += 64 * 256) {
        const int n  = e / (KPAD / 2);
        const int kp = (e % (KPAD / 2)) * 2;
        float2 v = make_float2(0.f, 0.f);
        if (kp < F_IN) v = *(const float2*)(w + (size_t)n * F_IN + kp);
        __nv_bfloat162 hi2 = __floats2bfloat162_rn(v.x, v.y);
        float2 hf = __bfloat1622float2(hi2);
        __nv_bfloat162 lo2 = __floats2bfloat162_rn(v.x - hf.x, v.y - hf.y);
        *(__nv_bfloat162*)(g_wh + (size_t)n * KPAD + kp) = hi2;
        *(__nv_bfloat162*)(g_wl + (size_t)n * KPAD + kp) = lo2;
    }
}

// ---------------- K1: o1_raw = x @ w^T via wmma bf16 2-term split ------------
#define BK 32
#define NCH (KPAD / BK)   // 25
#define LDS_T 40          // 32 + 8 pad (bf16 elems)

__global__ __launch_bounds__(256) void k1_gemm_wmma(const float* __restrict__ x)
{
    __shared__ __nv_bfloat16 sAh[64][LDS_T];
    __shared__ __nv_bfloat16 sAl[64][LDS_T];
    __shared__ __nv_bfloat16 sBh[128][LDS_T];
    __shared__ __nv_bfloat16 sBl[128][LDS_T];

    const int t = threadIdx.x;
    const int wid = t >> 5;
    const int wr = wid >> 1;           // 0..3  (M quadrant, 16 rows)
    const int wc = wid & 1;            // 0..1  (N half, 64 cols)
    const int row0 = blockIdx.x * 64;

    if (blockIdx.x == 0 && t < H) { g_sum[t] = 0.0; g_sumsq[t] = 0.0; }

    wmma::fragment<wmma::accumulator, 16, 16, 16, float> acc[4];
#pragma unroll
    for (int j = 0; j < 4; j++) wmma::fill_fragment(acc[j], 0.f);

    for (int c = 0; c < NCH; c++) {
        const int kc = c * BK;
#pragma unroll
        for (int it = 0; it < 4; it++) {
            const int e = t + it * 256;
            const int m  = e >> 4;
            const int kp = (e & 15) * 2;
            const int k  = kc + kp;
            float2 v = make_float2(0.f, 0.f);
            if (k < F_IN) v = *(const float2*)(x + (size_t)(row0 + m) * F_IN + k);
            __nv_bfloat162 hi2 = __floats2bfloat162_rn(v.x, v.y);
            float2 hf = __bfloat1622float2(hi2);
            __nv_bfloat162 lo2 = __floats2bfloat162_rn(v.x - hf.x, v.y - hf.y);
            *(__nv_bfloat162*)(&sAh[m][kp]) = hi2;
            *(__nv_bfloat162*)(&sAl[m][kp]) = lo2;
        }
#pragma unroll
        for (int it = 0; it < 8; it++) {
            const int e = t + it * 256;
            const int n  = e >> 4;
            const int kp = (e & 15) * 2;
            const size_t gi = (size_t)n * KPAD + kc + kp;
            *(uint32_t*)(&sBh[n][kp]) = *(const uint32_t*)(g_wh + gi);
            *(uint32_t*)(&sBl[n][kp]) = *(const uint32_t*)(g_wl + gi);
        }
        __syncthreads();

#pragma unroll
        for (int kk = 0; kk < 2; kk++) {
            wmma::fragment<wmma::matrix_a, 16, 16, 16, __nv_bfloat16, wmma::row_major> ah, al;
            wmma::load_matrix_sync(ah, &sAh[wr * 16][kk * 16], LDS_T);
            wmma::load_matrix_sync(al, &sAl[wr * 16][kk * 16], LDS_T);
#pragma unroll
            for (int j = 0; j < 4; j++) {
                wmma::fragment<wmma::matrix_b, 16, 16, 16, __nv_bfloat16, wmma::col_major> bh, bl;
                wmma::load_matrix_sync(bh, &sBh[wc * 64 + j * 16][kk * 16], LDS_T);
                wmma::load_matrix_sync(bl, &sBl[wc * 64 + j * 16][kk * 16], LDS_T);
                wmma::mma_sync(acc[j], ah, bh, acc[j]);
                wmma::mma_sync(acc[j], ah, bl, acc[j]);
                wmma::mma_sync(acc[j], al, bh, acc[j]);
            }
        }
        __syncthreads();
    }

#pragma unroll
    for (int j = 0; j < 4; j++) {
        float* dst = g_o1 + (size_t)(row0 + wr * 16) * H + wc * 64 + j * 16;
        wmma::store_matrix_sync(dst, acc[j], H, wmma::mem_row_major);
    }
}

// ---------------- K2: bias + selu + BN stats (in-place on g_o1) --------------
__global__ __launch_bounds__(256) void k2_stats(const float* __restrict__ bias)
{
    const int col = threadIdx.x & (H - 1);
    const int rl  = threadIdx.x >> 7;            // 0 or 1
    const float b = bias[col];
    const int rend = blockIdx.x * 64 + 64;       // grid 128
    float s = 0.f, s2 = 0.f;
    for (int r = blockIdx.x * 64 + rl; r < rend; r += 2) {
        const size_t idx = (size_t)r * H + col;
        float v = selu_f(g_o1[idx] + b);
        g_o1[idx] = v;
        s += v;
        s2 = fmaf(v, v, s2);
    }
    atomicAdd(&g_sum[col],   (double)s);
    atomicAdd(&g_sumsq[col], (double)s2);
}

// ---------------- K3: BN apply + fc2 + selu -> o[n,2] (1 row per warp) -------
__global__ __launch_bounds__(256) void k3_bn_fc2(
    const float* __restrict__ gamma, const float* __restrict__ beta,
    const float* __restrict__ w2, const float* __restrict__ b2,
    float* __restrict__ out_tail, int write_tail)
{
    __shared__ float s_scale[H], s_shift[H], s_w0[H], s_w1[H];
    const int t = threadIdx.x;
    if (blockIdx.x == 0 && t == 0) g_denom = 0.0;
    if (t < H) {
        double mean = g_sum[t]   / (double)N_ROWS;
        double var  = g_sumsq[t] / (double)N_ROWS - mean * mean;
        float inv = (float)rsqrt(var + 1e-5);
        float sc  = gamma[t] * inv;
        s_scale[t] = sc;
        s_shift[t] = beta[t] - (float)mean * sc;
        s_w0[t] = w2[t];
        s_w1[t] = w2[H + t];
    }
    __syncthreads();

    const int warp = t >> 5, lane = t & 31;
    const int row = blockIdx.x * 8 + warp;       // grid 1024 -> all 8192 rows

    float4 v = *(const float4*)(g_o1 + (size_t)row * H + lane * 4);
    const int c = lane * 4;
    float d0 = 0.f, d1 = 0.f;
    float bn;
    bn = fmaf(v.x, s_scale[c + 0], s_shift[c + 0]);
    d0 = fmaf(bn, s_w0[c + 0], d0); d1 = fmaf(bn, s_w1[c + 0], d1);
    bn = fmaf(v.y, s_scale[c + 1], s_shift[c + 1]);
    d0 = fmaf(bn, s_w0[c + 1], d0); d1 = fmaf(bn, s_w1[c + 1], d1);
    bn = fmaf(v.z, s_scale[c + 2], s_shift[c + 2]);
    d0 = fmaf(bn, s_w0[c + 2], d0); d1 = fmaf(bn, s_w1[c + 2], d1);
    bn = fmaf(v.w, s_scale[c + 3], s_shift[c + 3]);
    d0 = fmaf(bn, s_w0[c + 3], d0); d1 = fmaf(bn, s_w1[c + 3], d1);
#pragma unroll
    for (int off = 16; off > 0; off >>= 1) {
        d0 += __shfl_down_sync(0xffffffffu, d0, off);
        d1 += __shfl_down_sync(0xffffffffu, d1, off);
    }
    if (lane == 0) {
        float o0 = selu_f(d0 + b2[0]);
        float o1 = selu_f(d1 + b2[1]);
        g_o[row] = make_float2(o0, o1);
        if (write_tail) {
            out_tail[row * 2 + 0] = o0;
            out_tail[row * 2 + 1] = o1;
        }
    }
}

// ---------------- K4: S = sum_{i<j} 1/(1+d_ij)  (symmetry-halved) ------------
// grid 8192 = 1024 strips(8 rows) x 8 j-tiles(1024). Below-diagonal tiles exit.
__global__ __launch_bounds__(256) void k4_denom()
{
    __shared__ float sx[JT], sy[JT];
    const int t     = threadIdx.x;
    const int rid   = blockIdx.x >> 3;
    const int jt    = blockIdx.x & 7;
    const int i0    = rid * 8;
    const int jbase = jt * JT;
    if (jbase + JT - 1 <= i0) return;            // all j <= min i: no j>i pairs

    const float2* __restrict__ src = g_o + jbase;
    for (int i = t; i < JT; i += 256) {
        float2 v = src[i];
        sx[i] = v.x; sy[i] = v.y;
    }
    float2 p[8];
#pragma unroll
    for (int u = 0; u < 8; u++) p[u] = g_o[i0 + u];
    __syncthreads();

    float acc = 0.f;
    const int j4 = t * 4;
    if (jbase >= i0 + 8) {
        // clean tile: every j > every i; packed f32x2 + paired reciprocal
        ull m1, on;
        PACK_F32X2(m1, -1.f, -1.f);
        PACK_F32X2(on,  1.f,  1.f);
        ull qx0 = *(const ull*)&sx[j4];
        ull qx1 = *(const ull*)&sx[j4 + 2];
        ull qy0 = *(const ull*)&sy[j4];
        ull qy1 = *(const ull*)&sy[j4 + 2];
        float a0 = 0.f, a1 = 0.f;
#pragma unroll
        for (int u = 0; u < 8; u++) {
            ull ppx, ppy;
            PACK_F32X2(ppx, p[u].x, p[u].x);
            PACK_F32X2(ppy, p[u].y, p[u].y);
            ull dxA, dyA, tA, dA, dxB, dyB, tB, dB;
            FMA_F32X2(dxA, qx0, m1, ppx);
            FMA_F32X2(dyA, qy0, m1, ppy);
            FMA_F32X2(tA, dyA, dyA, on);
            FMA_F32X2(dA, dxA, dxA, tA);
            FMA_F32X2(dxB, qx1, m1, ppx);
            FMA_F32X2(dyB, qy1, m1, ppy);
            FMA_F32X2(tB, dyB, dyB, on);
            FMA_F32X2(dB, dxB, dxB, tB);
            float vA0, vA1, vB0, vB1;
            UNPACK_F32X2(vA0, vA1, dA);
            UNPACK_F32X2(vB0, vB1, dB);
            a0 = fmaf(vA0 + vA1, frcp(vA0 * vA1), a0);
            a1 = fmaf(vB0 + vB1, frcp(vB0 * vB1), a1);
        }
        acc = a0 + a1;
    } else {
        // straddle tile: scalar masked (j > i)
#pragma unroll
        for (int uu = 0; uu < 4; uu++) {
            const int j = jbase + j4 + uu;
            const float qx = sx[j4 + uu], qy = sy[j4 + uu];
#pragma unroll
            for (int u = 0; u < 8; u++) {
                const float dx = p[u].x - qx;
                const float dy = p[u].y - qy;
                const float d  = fmaf(dx, dx, fmaf(dy, dy, 1.f));
                if (j > i0 + u) acc += frcp(d);
            }
        }
    }

    float s = acc;
#pragma unroll
    for (int off = 16; off > 0; off >>= 1)
        s += __shfl_down_sync(0xffffffffu, s, off);
    __shared__ float red[8];
    if ((t & 31) == 0) red[t >> 5] = s;
    __syncthreads();
    if (t == 0) {
        float tot = 0.f;
#pragma unroll
        for (int u = 0; u < 8; u++) tot += red[u];
        atomicAdd(&g_denom, (double)tot);
    }
}

// ---------------- K5: qij write; inv = 1/(2*S) folded in ---------------------
__global__ __launch_bounds__(256) void k5_qij(float* __restrict__ out)
{
    __shared__ float sx[JH], sy[JH];
    __shared__ float s_inv;
    const int t    = threadIdx.x;
    const int half = blockIdx.x & 1;
    const int rid  = blockIdx.x >> 1;

    if (t == 0) s_inv = (float)(1.0 / (2.0 * g_denom));
    const float2* __restrict__ src = g_o + half * JH;
    for (int i = t; i < JH; i += 256) {
        float2 v = src[i];
        sx[i] = v.x; sy[i] = v.y;
    }
    __syncthreads();

    const float inv = s_inv;
    ull m1, on;
    PACK_F32X2(m1, -1.f, -1.f);
    PACK_F32X2(on,  1.f,  1.f);

#pragma unroll
    for (int r = 0; r < 8; r++) {
        const int row = rid * 8 + r;
        float2 p = g_o[row];
        ull ppx, ppy;
        PACK_F32X2(ppx, p.x, p.x);
        PACK_F32X2(ppy, p.y, p.y);
        float4* __restrict__ dst = (float4*)(out + (size_t)row * N_ROWS + half * JH);
        for (int c = t; c < JH / 4; c += 256) {
            ull qx0 = *(const ull*)&sx[c * 4];
            ull qx1 = *(const ull*)&sx[c * 4 + 2];
            ull qy0 = *(const ull*)&sy[c * 4];
            ull qy1 = *(const ull*)&sy[c * 4 + 2];
            ull dxA, dyA, tA, dA, dxB, dyB, tB, dB;
            FMA_F32X2(dxA, qx0, m1, ppx);
            FMA_F32X2(dyA, qy0, m1, ppy);
            FMA_F32X2(tA, dyA, dyA, on);
            FMA_F32X2(dA, dxA, dxA, tA);
            FMA_F32X2(dxB, qx1, m1, ppx);
            FMA_F32X2(dyB, qy1, m1, ppy);
            FMA_F32X2(tB, dyB, dyB, on);
            FMA_F32X2(dB, dxB, dxB, tB);
            float d0, d1, d2, d3;
            UNPACK_F32X2(d0, d1, dA);
            UNPACK_F32X2(d2, d3, dB);
            float4 o4;
            o4.x = frcp(d0) * inv;
            o4.y = frcp(d1) * inv;
            o4.z = frcp(d2) * inv;
            o4.w = frcp(d3) * inv;
            __stcs(dst + c, o4);
        }
    }
}

// ---------------- launch -----------------------------------------------------
extern "C" void kernel_launch(void* const* d_in, const int* in_sizes, int n_in,
                              void* d_out, int out_size)
{
    const float* x     = (const float*)d_in[0];
    const float* fcw   = (const float*)d_in[1];
    const float* fcb   = (const float*)d_in[2];
    const float* gamma = (const float*)d_in[3];
    const float* beta  = (const float*)d_in[4];
    const float* w2    = (const float*)d_in[5];
    const float* b2    = (const float*)d_in[6];
    float* out = (float*)d_out;

    const size_t nq = (size_t)N_ROWS * N_ROWS;
    const int write_tail = ((size_t)out_size > nq) ? 1 : 0;

    k0_wprep<<<64, 256>>>(fcw);
    k1_gemm_wmma<<<128, 256>>>(x);
    k2_stats<<<128, 256>>>(fcb);
    k3_bn_fc2<<<1024, 256>>>(gamma, beta, w2, b2, out + nq, write_tail);
    k4_denom<<<8192, 256>>>();
    k5_qij<<<2048, 256>>>(out);
}